// round 2
// baseline (speedup 1.0000x reference)
#include <cuda_runtime.h>
#include <cstddef>
#include <cstdint>

#define HW 4096          // 64*64 spatial positions
#define B  2             // batch

// ---------------------------------------------------------------------------
// Scratch (static device globals — no allocation allowed in kernel_launch)
// ---------------------------------------------------------------------------
__device__ float g_M [(size_t)B * HW * HW];   // M[b][j][i] = relu(c3n)*relu(c4n)
__device__ float g_MT[(size_t)B * HW * HW];   // M transposed: MT[b][i][j]
__device__ float g_inorm[4][B * HW];          // 0:src3 1:tgt3 2:src4 3:tgt4

// ---------------------------------------------------------------------------
// 1) inverse L2 norms over channel dim:  1/sqrt(sum_c f^2 + 1e-6)
//    feat layout: [b][c][p], p contiguous (4096)
// ---------------------------------------------------------------------------
__global__ void inv_norm_kernel(const float* __restrict__ f, int slot, int K)
{
    __shared__ float red[4][64];
    int sl = threadIdx.x;          // 0..63 (spatial, coalesced)
    int cg = threadIdx.y;          // 0..3  (channel group)
    int p  = blockIdx.x * 64 + sl; // 0..8191
    int b  = p >> 12;
    int s  = p & (HW - 1);

    const float* fp = f + (size_t)b * K * HW + s;
    int kq = K >> 2;
    int c0 = cg * kq, c1 = c0 + kq;
    float sum = 0.f;
    #pragma unroll 4
    for (int c = c0; c < c1; c++) {
        float v = __ldg(fp + (size_t)c * HW);
        sum = fmaf(v, v, sum);
    }
    red[cg][sl] = sum;
    __syncthreads();
    if (cg == 0) {
        float t = red[0][sl] + red[1][sl] + red[2][sl] + red[3][sl];
        g_inorm[slot][p] = 1.0f / sqrtf(t + 1e-6f);
    }
}

// ---------------------------------------------------------------------------
// 2) fused correlation GEMM:  C[j][i] = relu( inA[j]*inB[i] * sum_k A[k][j]B[k][i] )
//    mode 0: M = C ;  mode 1: M *= C
//    128x128 tile, 256 threads, 8x8 per thread, K-step 8, reg double-buffer
// ---------------------------------------------------------------------------
__global__ __launch_bounds__(256, 2)
void gemm_relu_kernel(const float* __restrict__ A,   // tgt feat [b][K][HW]
                      const float* __restrict__ Bm,  // src feat [b][K][HW]
                      int slotA, int slotB, int K, int mode)
{
    int b = blockIdx.z;
    const float* Ab = A  + (size_t)b * K * HW;
    const float* Bb = Bm + (size_t)b * K * HW;
    float*       Mb = g_M + (size_t)b * HW * HW;

    int j0 = blockIdx.y * 128;
    int i0 = blockIdx.x * 128;

    __shared__ float As[8][128];
    __shared__ float Bs[8][128];

    int tid = threadIdx.x;
    int lr  = tid >> 5;            // 0..7  (k row for loads)
    int lc  = (tid & 31) << 2;     // 0..124 (float4 col)
    int tx  = tid & 15;            // i micro-tile
    int ty  = tid >> 4;            // j micro-tile

    float acc[8][8];
    #pragma unroll
    for (int r = 0; r < 8; r++)
        #pragma unroll
        for (int c = 0; c < 8; c++) acc[r][c] = 0.f;

    const float* Aptr = Ab + (size_t)lr * HW + j0 + lc;
    const float* Bptr = Bb + (size_t)lr * HW + i0 + lc;

    float4 aReg = *(const float4*)Aptr;
    float4 bReg = *(const float4*)Bptr;

    int kTiles = K >> 3;
    for (int kt = 0; kt < kTiles; kt++) {
        *(float4*)&As[lr][lc] = aReg;
        *(float4*)&Bs[lr][lc] = bReg;
        __syncthreads();
        if (kt + 1 < kTiles) {
            aReg = *(const float4*)(Aptr + (size_t)(kt + 1) * 8 * HW);
            bReg = *(const float4*)(Bptr + (size_t)(kt + 1) * 8 * HW);
        }
        #pragma unroll
        for (int kk = 0; kk < 8; kk++) {
            float af[8], bf[8];
            #pragma unroll
            for (int r = 0; r < 8; r++) af[r] = As[kk][ty * 8 + r];
            #pragma unroll
            for (int c = 0; c < 8; c++) bf[c] = Bs[kk][tx * 8 + c];
            #pragma unroll
            for (int r = 0; r < 8; r++)
                #pragma unroll
                for (int c = 0; c < 8; c++)
                    acc[r][c] = fmaf(af[r], bf[c], acc[r][c]);
        }
        __syncthreads();
    }

    // epilogue: scale by inverse norms, relu, write / multiply
    float si[8];
    #pragma unroll
    for (int c = 0; c < 8; c++) si[c] = g_inorm[slotB][b * HW + i0 + tx * 8 + c];

    #pragma unroll
    for (int r = 0; r < 8; r++) {
        int j = j0 + ty * 8 + r;
        float sj = g_inorm[slotA][b * HW + j];
        size_t rowoff = (size_t)j * HW + i0 + tx * 8;
        #pragma unroll
        for (int c = 0; c < 8; c++) {
            float v = fmaxf(acc[r][c] * sj * si[c], 0.f);
            if (mode) Mb[rowoff + c] *= v;
            else      Mb[rowoff + c]  = v;
        }
    }
}

// ---------------------------------------------------------------------------
// 3) transpose M -> MT (per batch 4096x4096), 32x32 smem tiles
// ---------------------------------------------------------------------------
__global__ void transpose_kernel()
{
    __shared__ float tile[32][33];
    int b = blockIdx.z;
    const float* ib = g_M  + (size_t)b * HW * HW;
    float*       ob = g_MT + (size_t)b * HW * HW;

    int x  = blockIdx.x * 32 + threadIdx.x;
    int y0 = blockIdx.y * 32;
    #pragma unroll
    for (int r = 0; r < 4; r++)
        tile[threadIdx.y + r * 8][threadIdx.x] =
            ib[(size_t)(y0 + threadIdx.y + r * 8) * HW + x];
    __syncthreads();
    int x2 = blockIdx.y * 32 + threadIdx.x;
    int y2 = blockIdx.x * 32;
    #pragma unroll
    for (int r = 0; r < 4; r++)
        ob[(size_t)(y2 + threadIdx.y + r * 8) * HW + x2] =
            tile[threadIdx.x][threadIdx.y + r * 8];
}

// ---------------------------------------------------------------------------
// 4) kernel-soft-argmax, one block per row (4096 elements, fits in smem)
//    useMT=1 : rows of MT (= columns of M)  -> s2t grid
//    useMT=0 : rows of M                    -> t2s grid
//    softmax computed WITHOUT max subtraction: exp arg in [0, 50], safe in fp32,
//    identical ratio p_j to the reference (constant factor cancels).
// ---------------------------------------------------------------------------
__global__ __launch_bounds__(256)
void soft_argmax_kernel(int useMT, float* __restrict__ outG)
{
    __shared__ float srow[HW];     // 16 KB
    __shared__ float gx[64], gy[64];
    __shared__ float wsum[8], wmax[8], wS[8], wSY[8];
    __shared__ int   widx[8];
    __shared__ float s_alpha;
    __shared__ int   s_xs, s_ys;

    int row = blockIdx.x & (HW - 1);
    int b   = blockIdx.x >> 12;
    const float* base = useMT ? g_MT : g_M;
    const float4* rp  = (const float4*)(base + (size_t)blockIdx.x * HW);

    int tid  = threadIdx.x;
    int warp = tid >> 5;
    int lane = tid & 31;

    // load row (coalesced float4)
    #pragma unroll
    for (int q = 0; q < 4; q++) {
        float4 v = rp[q * 256 + tid];
        *(float4*)&srow[(q * 256 + tid) * 4] = v;
    }
    __syncthreads();

    // ---- pass A: sum of squares + argmax (first-occurrence tie-break) ----
    float sumsq = 0.f, vmax = -1.f;
    int   imax  = 0;
    #pragma unroll
    for (int q = 0; q < 16; q++) {
        int a = q * 256 + tid;
        float v = srow[a];
        sumsq = fmaf(v, v, sumsq);
        if (v > vmax) { vmax = v; imax = a; }
    }
    #pragma unroll
    for (int off = 16; off > 0; off >>= 1) {
        sumsq += __shfl_down_sync(0xffffffffu, sumsq, off);
        float ov = __shfl_down_sync(0xffffffffu, vmax, off);
        int   oi = __shfl_down_sync(0xffffffffu, imax, off);
        if (ov > vmax || (ov == vmax && oi < imax)) { vmax = ov; imax = oi; }
    }
    if (lane == 0) { wsum[warp] = sumsq; wmax[warp] = vmax; widx[warp] = imax; }
    __syncthreads();
    if (tid == 0) {
        float ss = 0.f, vm = -1.f; int im = 0;
        #pragma unroll
        for (int w = 0; w < 8; w++) {
            ss += wsum[w];
            if (wmax[w] > vm || (wmax[w] == vm && widx[w] < im)) { vm = wmax[w]; im = widx[w]; }
        }
        float norm = sqrtf(ss + 1e-6f);
        s_alpha = 50.f / norm;
        s_xs = im & 63;
        s_ys = im >> 6;
    }
    __syncthreads();

    // separable gaussian tables: exp(-d^2 / (2*sigma^2)), sigma=5 -> *0.02
    if (tid < 64) {
        float dx = (float)(tid - s_xs);
        gx[tid] = __expf(-dx * dx * 0.02f);
    } else if (tid < 128) {
        float dy = (float)((tid - 64) - s_ys);
        gy[tid - 64] = __expf(-dy * dy * 0.02f);
    }
    __syncthreads();

    // ---- pass B: softmax-weighted coordinate sums ----
    float alpha = s_alpha;
    int   xa    = tid & 63;             // constant per thread (256 % 64 == 0)
    float gxv   = gx[xa];
    float xn    = fmaf((float)xa, 2.f / 63.f, -1.f);

    float s = 0.f, sy = 0.f;
    #pragma unroll
    for (int q = 0; q < 16; q++) {
        int a  = q * 256 + tid;
        int ya = a >> 6;
        float v = srow[a];
        float e = __expf(alpha * gxv * gy[ya] * v);
        s += e;
        sy = fmaf(e, fmaf((float)ya, 2.f / 63.f, -1.f), sy);
    }
    float sx = s * xn;

    #pragma unroll
    for (int off = 16; off > 0; off >>= 1) {
        s  += __shfl_down_sync(0xffffffffu, s,  off);
        sx += __shfl_down_sync(0xffffffffu, sx, off);
        sy += __shfl_down_sync(0xffffffffu, sy, off);
    }
    if (lane == 0) { wS[warp] = s; wsum[warp] = sx; wSY[warp] = sy; }
    __syncthreads();
    if (tid == 0) {
        float S = 0.f, SX = 0.f, SY = 0.f;
        #pragma unroll
        for (int w = 0; w < 8; w++) { S += wS[w]; SX += wsum[w]; SY += wSY[w]; }
        int yr = row >> 6, xr = row & 63;
        size_t o = ((size_t)(b * 64 + yr) * 64 + xr) * 2;
        outG[o + 0] = SX / S;
        outG[o + 1] = SY / S;
    }
}

// ---------------------------------------------------------------------------
// launch
// ---------------------------------------------------------------------------
extern "C" void kernel_launch(void* const* d_in, const int* in_sizes, int n_in,
                              void* d_out, int out_size)
{
    const float* src3 = (const float*)d_in[0];
    const float* tgt3 = (const float*)d_in[1];
    const float* src4 = (const float*)d_in[2];
    const float* tgt4 = (const float*)d_in[3];
    float* out = (float*)d_out;

    // inverse norms (slots: 0 src3, 1 tgt3, 2 src4, 3 tgt4)
    dim3 nblk(64, 4);
    inv_norm_kernel<<<128, nblk>>>(src3, 0, 1024);
    inv_norm_kernel<<<128, nblk>>>(tgt3, 1, 1024);
    inv_norm_kernel<<<128, nblk>>>(src4, 2, 2048);
    inv_norm_kernel<<<128, nblk>>>(tgt4, 3, 2048);

    // M = relu(c3n) ; M *= relu(c4n)    (corr[j,i] = <tgt[:,j], src[:,i]>)
    dim3 gg(HW / 128, HW / 128, B);
    gemm_relu_kernel<<<gg, 256>>>(tgt3, src3, 1, 0, 1024, 0);
    gemm_relu_kernel<<<gg, 256>>>(tgt4, src4, 3, 2, 2048, 1);

    // MT for the s2t (column) direction
    transpose_kernel<<<dim3(HW / 32, HW / 32, B), dim3(32, 8)>>>();

    // s2t: columns of M (= rows of MT) -> out[0 .. 16383]
    soft_argmax_kernel<<<B * HW, 256>>>(1, out);
    // t2s: rows of M -> out[32768 .. 49151]
    soft_argmax_kernel<<<B * HW, 256>>>(0, out + 32768);

    // flows are exactly zero in the reference
    cudaMemsetAsync(out + 16384, 0, 16384 * sizeof(float));
    cudaMemsetAsync(out + 49152, 0, 16384 * sizeof(float));
}